// round 9
// baseline (speedup 1.0000x reference)
#include <cuda_runtime.h>
#include <cuda_bf16.h>

#define HASH_SIZE 256
#define OFFSET_SIZE 64

// L2 evict-last policy for the 3MB offset table (heavy reuse).
__device__ __forceinline__ long long make_evict_last_policy() {
    long long p;
    asm("createpolicy.fractional.L2::evict_last.b64 %0, 1.0;" : "=l"(p));
    return p;
}

__device__ __forceinline__ int ldg_hint_s32(const int* ptr, long long pol) {
    int v;
    asm volatile("ld.global.L2::cache_hint.s32 %0, [%1], %2;"
                 : "=r"(v) : "l"(ptr), "l"(pol));
    return v;
}

__global__ __launch_bounds__(256) void psh_kernel(
    const int*    __restrict__ coords,       // [N,3] int32
    const float4* __restrict__ hash_table,   // [256,256,256,8] f32 as float4 pairs
    const int*    __restrict__ offset_table, // [64,64,64,3] int32
    const float*  __restrict__ m0,           // [3]
    const float*  __restrict__ m1,           // [3]
    float4*       __restrict__ out,          // [N,8] f32 as float4 pairs
    int n)                                   // n = number of queries (even here: 4M)
{
    const float m0x = m0[0], m0y = m0[1], m0z = m0[2];
    const float m1x = m1[0], m1y = m1[1], m1z = m1[2];

    const long long pol = make_evict_last_policy();

    // Each thread handles queries 2t and 2t+1 -> two independent memory chains.
    int t = blockIdx.x * blockDim.x + threadIdx.x;
    int i0 = 2 * t;
    if (i0 >= n) return;

    // --- coords: 6 ints per thread, three aligned 64-bit streaming loads ---
    const int2* cp = (const int2*)(coords + 3 * i0);   // 24B-aligned (24*t)
    const int2 w0 = __ldcs(cp + 0);   // c0a, c1a
    const int2 w1 = __ldcs(cp + 1);   // c2a, c0b
    const int2 w2 = __ldcs(cp + 2);   // c1b, c2b

    const int c0a = w0.x, c1a = w0.y, c2a = w1.x;
    const int c0b = w1.y, c1b = w2.x, c2b = w2.y;

    // --- offset-table indices (both queries) ---
    const int oa0 = ((int)((float)c0a * m1x)) & (OFFSET_SIZE - 1);
    const int oa1 = ((int)((float)c1a * m1y)) & (OFFSET_SIZE - 1);
    const int oa2 = ((int)((float)c2a * m1z)) & (OFFSET_SIZE - 1);
    const int ob0 = ((int)((float)c0b * m1x)) & (OFFSET_SIZE - 1);
    const int ob1 = ((int)((float)c1b * m1y)) & (OFFSET_SIZE - 1);
    const int ob2 = ((int)((float)c2b * m1z)) & (OFFSET_SIZE - 1);
    const int obaseA = ((((oa0 << 6) | oa1) << 6) | oa2) * 3;
    const int obaseB = ((((ob0 << 6) | ob1) << 6) | ob2) * 3;

    // --- offset gathers: issue both chains' loads back-to-back (MLP=6) ---
    const int fa0 = ldg_hint_s32(&offset_table[obaseA + 0], pol);
    const int fa1 = ldg_hint_s32(&offset_table[obaseA + 1], pol);
    const int fa2 = ldg_hint_s32(&offset_table[obaseA + 2], pol);
    const int fb0 = ldg_hint_s32(&offset_table[obaseB + 0], pol);
    const int fb1 = ldg_hint_s32(&offset_table[obaseB + 1], pol);
    const int fb2 = ldg_hint_s32(&offset_table[obaseB + 2], pol);

    // --- hash indices ---
    const int ha0 = (((int)((float)c0a * m0x)) + fa0) & (HASH_SIZE - 1);
    const int ha1 = (((int)((float)c1a * m0y)) + fa1) & (HASH_SIZE - 1);
    const int ha2 = (((int)((float)c2a * m0z)) + fa2) & (HASH_SIZE - 1);
    const int hb0 = (((int)((float)c0b * m0x)) + fb0) & (HASH_SIZE - 1);
    const int hb1 = (((int)((float)c1b * m0y)) + fb1) & (HASH_SIZE - 1);
    const int hb2 = (((int)((float)c2b * m0z)) + fb2) & (HASH_SIZE - 1);

    const long long rowA = (long long)((((ha0 << 8) | ha1) << 8) | ha2) * 2;
    const long long rowB = (long long)((((hb0 << 8) | hb1) << 8) | hb2) * 2;

    // --- hash gathers: 4 independent 128-bit loads in flight (default policy,
    //     which beat evict_first in the A/B) ---
    const float4 a0 = __ldg(&hash_table[rowA + 0]);
    const float4 a1 = __ldg(&hash_table[rowA + 1]);
    const float4 b0 = __ldg(&hash_table[rowB + 0]);
    const float4 b1 = __ldg(&hash_table[rowB + 1]);

    // --- output: 64B contiguous per thread, streaming stores ---
    float4* op = out + 4ll * t;
    __stcs(op + 0, a0);
    __stcs(op + 1, a1);
    __stcs(op + 2, b0);
    __stcs(op + 3, b1);
}

extern "C" void kernel_launch(void* const* d_in, const int* in_sizes, int n_in,
                              void* d_out, int out_size) {
    const int*    coords       = (const int*)d_in[0];
    const float4* hash_table   = (const float4*)d_in[1];
    const int*    offset_table = (const int*)d_in[2];
    const float*  m0           = (const float*)d_in[3];
    const float*  m1           = (const float*)d_in[4];
    float4*       out          = (float4*)d_out;

    const int n = in_sizes[0] / 3;        // number of queries (4,000,000 -> even)
    const int threads = 256;
    const int nthreads = (n + 1) / 2;     // 2 queries per thread
    const int blocks = (nthreads + threads - 1) / threads;
    psh_kernel<<<blocks, threads>>>(coords, hash_table, offset_table, m0, m1, out, n);
}

// round 10
// speedup vs baseline: 1.0707x; 1.0707x over previous
#include <cuda_runtime.h>
#include <cuda_bf16.h>

#define HASH_SIZE 256
#define OFFSET_SIZE 64
#define OFFSET_ENTRIES (OFFSET_SIZE * OFFSET_SIZE * OFFSET_SIZE)

// 1MB packed offset table: one uint32 per entry, f0 | f1<<8 | f2<<16.
// Offsets are only ever used mod 256, so 8 bits per component is lossless.
__device__ unsigned int g_packed_offsets[OFFSET_ENTRIES];

// L2 evict-last policy for the packed offset table (heavy reuse, 1MB).
__device__ __forceinline__ long long make_evict_last_policy() {
    long long p;
    asm("createpolicy.fractional.L2::evict_last.b64 %0, 1.0;" : "=l"(p));
    return p;
}

__device__ __forceinline__ unsigned int ldg_hint_u32(const unsigned int* ptr, long long pol) {
    unsigned int v;
    asm volatile("ld.global.L2::cache_hint.u32 %0, [%1], %2;"
                 : "=r"(v) : "l"(ptr), "l"(pol));
    return v;
}

// Prologue: pack [64^3][3] int32 -> [64^3] uint32 (bytes).
__global__ __launch_bounds__(256) void pack_offsets_kernel(
    const int* __restrict__ offset_table)
{
    int e = blockIdx.x * blockDim.x + threadIdx.x;
    if (e >= OFFSET_ENTRIES) return;
    const int f0 = offset_table[3 * e + 0] & 0xFF;
    const int f1 = offset_table[3 * e + 1] & 0xFF;
    const int f2 = offset_table[3 * e + 2] & 0xFF;
    g_packed_offsets[e] = (unsigned int)(f0 | (f1 << 8) | (f2 << 16));
}

__global__ __launch_bounds__(256) void psh_kernel(
    const int*    __restrict__ coords,       // [N,3] int32
    const float4* __restrict__ hash_table,   // [256,256,256,8] f32 as float4 pairs
    const float*  __restrict__ m0,           // [3]
    const float*  __restrict__ m1,           // [3]
    float4*       __restrict__ out,          // [N,8] f32 as float4 pairs
    int n)
{
    const float m0x = m0[0], m0y = m0[1], m0z = m0[2];
    const float m1x = m1[0], m1y = m1[1], m1z = m1[2];

    int i = blockIdx.x * blockDim.x + threadIdx.x;
    if (i >= n) return;

    const long long pol = make_evict_last_policy();

    // --- coords: dense, read-once -> streaming loads ---
    const int c0 = __ldcs(&coords[3 * i + 0]);
    const int c1 = __ldcs(&coords[3 * i + 1]);
    const int c2 = __ldcs(&coords[3 * i + 2]);

    // --- offset-table index: (int)(c * m1) & 63 (& == floor-mod for pow2) ---
    const int o0 = ((int)((float)c0 * m1x)) & (OFFSET_SIZE - 1);
    const int o1 = ((int)((float)c1 * m1y)) & (OFFSET_SIZE - 1);
    const int o2 = ((int)((float)c2 * m1z)) & (OFFSET_SIZE - 1);
    const int oent = (((o0 << 6) | o1) << 6) | o2;

    // --- single 4B gather into the 1MB packed table (L2-resident, evict_last) ---
    const unsigned int pf = ldg_hint_u32(&g_packed_offsets[oent], pol);
    const int f0 = (int)(pf & 0xFFu);
    const int f1 = (int)((pf >> 8) & 0xFFu);
    const int f2 = (int)((pf >> 16) & 0xFFu);

    // --- hash index: ((int)(c * m0) + off) & 255 (& == floor-mod for pow2) ---
    const int h0 = (((int)((float)c0 * m0x)) + f0) & (HASH_SIZE - 1);
    const int h1 = (((int)((float)c1 * m0y)) + f1) & (HASH_SIZE - 1);
    const int h2 = (((int)((float)c2 * m0z)) + f2) & (HASH_SIZE - 1);

    const long long row = (long long)((((h0 << 8) | h1) << 8) | h2) * 2;

    // --- hash gather: 32B row, default policy (best in A/B so far) ---
    const float4 a = __ldg(&hash_table[row + 0]);
    const float4 b = __ldg(&hash_table[row + 1]);

    // --- output: write-once -> streaming stores ---
    const long long ob = 2ll * i;
    __stcs(&out[ob + 0], a);
    __stcs(&out[ob + 1], b);
}

extern "C" void kernel_launch(void* const* d_in, const int* in_sizes, int n_in,
                              void* d_out, int out_size) {
    const int*    coords       = (const int*)d_in[0];
    const float4* hash_table   = (const float4*)d_in[1];
    const int*    offset_table = (const int*)d_in[2];
    const float*  m0           = (const float*)d_in[3];
    const float*  m1           = (const float*)d_in[4];
    float4*       out          = (float4*)d_out;

    // Prologue: pack the offset table (262144 entries).
    pack_offsets_kernel<<<(OFFSET_ENTRIES + 255) / 256, 256>>>(offset_table);

    const int n = in_sizes[0] / 3;  // number of queries
    const int threads = 256;
    const int blocks = (n + threads - 1) / threads;
    psh_kernel<<<blocks, threads>>>(coords, hash_table, m0, m1, out, n);
}